// round 7
// baseline (speedup 1.0000x reference)
#include <cuda_runtime.h>
#include <cstdint>
#include <cstddef>

#define NCH 128
#define MAXN 50000

// ---------------- scratch ----------------
__device__ float    g_h[(size_t)MAXN * NCH];
__device__ unsigned g_htf[(size_t)MAXN * NCH];   // tf32 copy of h for edge gather
__device__ float    g_agg[(size_t)MAXN * NCH];
__device__ unsigned g_wpack[118784];
__device__ int      g_is64;

#define OFF_MW1 0
#define OFF_MW2 36864
#define OFF_MW3 53248
#define OFF_W1  69632
#define OFF_W2  86016
#define OFF_W3  102400

// ---------------- helpers ----------------
__device__ __forceinline__ unsigned f2tf(float f) {
    unsigned u;
    asm("cvt.rna.tf32.f32 %0, %1;" : "=r"(u) : "f"(f));
    return u;
}

__device__ __forceinline__ void mma8(float c[4],
                                     unsigned a0, unsigned a1, unsigned a2, unsigned a3,
                                     unsigned b0, unsigned b1) {
    asm volatile(
        "mma.sync.aligned.m16n8k8.row.col.f32.tf32.tf32.f32 "
        "{%0,%1,%2,%3},{%4,%5,%6,%7},{%8,%9},{%0,%1,%2,%3};\n"
        : "+f"(c[0]), "+f"(c[1]), "+f"(c[2]), "+f"(c[3])
        : "r"(a0), "r"(a1), "r"(a2), "r"(a3), "r"(b0), "r"(b1));
}

__device__ __forceinline__ float gelu_exact(float x) {
    return 0.5f * x * (1.0f + erff(x * 0.70710678118654752f));
}

// cp.async
__device__ __forceinline__ void cpa16(unsigned dst, const void* src, int srcsize) {
    asm volatile("cp.async.cg.shared.global [%0], [%1], 16, %2;\n"
                 :: "r"(dst), "l"(src), "r"(srcsize) : "memory");
}
__device__ __forceinline__ void cpa_commit() {
    asm volatile("cp.async.commit_group;\n" ::: "memory");
}
__device__ __forceinline__ void cpa_wait1() {
    asm volatile("cp.async.wait_group 1;\n" ::: "memory");
}
__device__ __forceinline__ void cpa_wait0() {
    asm volatile("cp.async.wait_group 0;\n" ::: "memory");
}

// ---------------- mainloop: one K=32 chunk ----------------
__device__ __forceinline__ void mma_chunk_rm(float acc[4][4][4],
                                             const unsigned* __restrict__ sA, int stride, int kbase,
                                             const unsigned* __restrict__ sB,
                                             int wm, int wn, int lane) {
    const uint2* B2 = (const uint2*)sB;
#pragma unroll
    for (int kk = 0; kk < 4; kk++) {
        uint2 bf[4];
#pragma unroll
        for (int nt = 0; nt < 4; nt++)
            bf[nt] = B2[(kk * 16 + wn * 4 + nt) * 32 + lane];
#pragma unroll
        for (int mt = 0; mt < 4; mt++) {
            const unsigned* ap = sA + (wm * 64 + mt * 16 + (lane >> 2)) * stride
                                 + kbase + kk * 8 + (lane & 3);
            unsigned a0 = ap[0];
            unsigned a1 = ap[8 * stride];
            unsigned a2 = ap[4];
            unsigned a3 = ap[8 * stride + 4];
#pragma unroll
            for (int nt = 0; nt < 4; nt++)
                mma8(acc[mt][nt], a0, a1, a2, a3, bf[nt].x, bf[nt].y);
        }
    }
}

__device__ __forceinline__ void init_acc(float acc[4][4][4], const float* sBias, int wn, int lane) {
#pragma unroll
    for (int nt = 0; nt < 4; nt++) {
        int c = wn * 32 + nt * 8 + (lane & 3) * 2;
        float x0 = sBias[c], x1 = sBias[c + 1];
#pragma unroll
        for (int mt = 0; mt < 4; mt++) {
            acc[mt][nt][0] = x0; acc[mt][nt][1] = x1;
            acc[mt][nt][2] = x0; acc[mt][nt][3] = x1;
        }
    }
}

__device__ __forceinline__ void epi_tf32_gelu(float acc[4][4][4], unsigned* sM, int stride,
                                              int wm, int wn, int lane) {
#pragma unroll
    for (int mt = 0; mt < 4; mt++) {
        int r0 = wm * 64 + mt * 16 + (lane >> 2);
#pragma unroll
        for (int nt = 0; nt < 4; nt++) {
            int c0 = wn * 32 + nt * 8 + (lane & 3) * 2;
            uint2 u0, u1;
            u0.x = f2tf(gelu_exact(acc[mt][nt][0]));
            u0.y = f2tf(gelu_exact(acc[mt][nt][1]));
            u1.x = f2tf(gelu_exact(acc[mt][nt][2]));
            u1.y = f2tf(gelu_exact(acc[mt][nt][3]));
            *(uint2*)&sM[r0 * stride + c0] = u0;
            *(uint2*)&sM[(r0 + 8) * stride + c0] = u1;
        }
    }
}

__device__ __forceinline__ void epi_tf32_relu(float acc[4][4][4], unsigned* sM, int stride,
                                              int wm, int wn, int lane) {
#pragma unroll
    for (int mt = 0; mt < 4; mt++) {
        int r0 = wm * 64 + mt * 16 + (lane >> 2);
#pragma unroll
        for (int nt = 0; nt < 4; nt++) {
            int c0 = wn * 32 + nt * 8 + (lane & 3) * 2;
            uint2 u0, u1;
            u0.x = f2tf(fmaxf(acc[mt][nt][0], 0.f));
            u0.y = f2tf(fmaxf(acc[mt][nt][1], 0.f));
            u1.x = f2tf(fmaxf(acc[mt][nt][2], 0.f));
            u1.y = f2tf(fmaxf(acc[mt][nt][3], 0.f));
            *(uint2*)&sM[r0 * stride + c0] = u0;
            *(uint2*)&sM[(r0 + 8) * stride + c0] = u1;
        }
    }
}

// ---------------- misc kernels ----------------
__global__ void zero_kernel(float4* p, int n4) {
    int i = blockIdx.x * blockDim.x + threadIdx.x;
    if (i < n4) p[i] = make_float4(0.f, 0.f, 0.f, 0.f);
}

// detect int width + pack all six [K x 128] weights into tf32 fragment order
__global__ void prep_all(const float* __restrict__ mw1, const float* __restrict__ mw2,
                         const float* __restrict__ mw3, const float* __restrict__ w1,
                         const float* __restrict__ w2, const float* __restrict__ w3,
                         const void* __restrict__ ei, unsigned* __restrict__ wp) {
    int idx = blockIdx.x * blockDim.x + threadIdx.x;
    if (idx == 0) {
        const long long* p = (const long long*)ei;
        bool is64 = true;
        for (int i = 0; i < 8; i++) {
            long long v = p[i];
            if (v < 0 || v >= (1LL << 31)) is64 = false;
        }
        g_is64 = is64 ? 1 : 0;
    }
    if (idx >= 118784) return;
    const float* s;
    int loc = idx;
    if (idx < OFF_MW2)      { s = mw1; }
    else if (idx < OFF_MW3) { s = mw2; loc -= OFF_MW2; }
    else if (idx < OFF_W1)  { s = mw3; loc -= OFF_MW3; }
    else if (idx < OFF_W2)  { s = w1;  loc -= OFF_W1; }
    else if (idx < OFF_W3)  { s = w2;  loc -= OFF_W2; }
    else                    { s = w3;  loc -= OFF_W3; }
    int e = loc & 1;
    int lane = (loc >> 1) & 31;
    int u = (loc >> 6) & 15;
    int kk = (loc >> 10) & 3;
    int kc = loc >> 12;
    int k = kc * 32 + kk * 8 + e * 4 + (lane & 3);
    int n = u * 8 + (lane >> 2);
    wp[idx] = f2tf(s[(size_t)k * NCH + n]);
}

// ---------------- tf32 node GEMM (used for atomwise1 only) ----------------
__global__ void __launch_bounds__(256, 2)
node_gemm(const float* __restrict__ A,
          const unsigned* __restrict__ Wp, const float* __restrict__ bias,
          float* __restrict__ C, unsigned* __restrict__ Ctf, int M) {
    __shared__ __align__(16) unsigned sA[128 * 36];
    __shared__ __align__(16) unsigned sB[4096];
    __shared__ float sBias[128];
    const int tid = threadIdx.x;
    const int lane = tid & 31;
    const int warp = tid >> 5;
    const int wm = warp >> 2, wn = warp & 3;
    const int m0 = blockIdx.x * 128;

    if (tid < 128) sBias[tid] = bias[tid];
    __syncthreads();

    float acc[4][4][4];
    init_acc(acc, sBias, wn, lane);

#pragma unroll 1
    for (int kc = 0; kc < 4; kc++) {
#pragma unroll
        for (int i = 0; i < 4; i++) {
            int lin = tid + i * 256;
            int row = lin >> 3, c4 = lin & 7;
            float4 v = make_float4(0.f, 0.f, 0.f, 0.f);
            if (m0 + row < M)
                v = *(const float4*)(A + (size_t)(m0 + row) * NCH + kc * 32 + c4 * 4);
            uint4 u;
            u.x = f2tf(v.x); u.y = f2tf(v.y); u.z = f2tf(v.z); u.w = f2tf(v.w);
            *(uint4*)&sA[row * 36 + c4 * 4] = u;
        }
        const uint4* bs = (const uint4*)(Wp + (size_t)kc * 4096);
#pragma unroll
        for (int i = 0; i < 4; i++)
            ((uint4*)sB)[tid + i * 256] = bs[tid + i * 256];
        __syncthreads();
        mma_chunk_rm(acc, sA, 36, 0, sB, wm, wn, lane);
        __syncthreads();
    }

#pragma unroll
    for (int mt = 0; mt < 4; mt++) {
        int r0 = m0 + wm * 64 + mt * 16 + (lane >> 2);
#pragma unroll
        for (int nt = 0; nt < 4; nt++) {
            int c0 = wn * 32 + nt * 8 + (lane & 3) * 2;
            float v0 = acc[mt][nt][0], v1 = acc[mt][nt][1];
            float v2 = acc[mt][nt][2], v3 = acc[mt][nt][3];
            if (r0 < M) {
                *(float2*)(C + (size_t)r0 * NCH + c0) = make_float2(v0, v1);
                uint2 u; u.x = f2tf(v0); u.y = f2tf(v1);
                *(uint2*)(Ctf + (size_t)r0 * NCH + c0) = u;
            }
            if (r0 + 8 < M) {
                *(float2*)(C + (size_t)(r0 + 8) * NCH + c0) = make_float2(v2, v3);
                uint2 u; u.x = f2tf(v2); u.y = f2tf(v3);
                *(uint2*)(Ctf + (size_t)(r0 + 8) * NCH + c0) = u;
            }
        }
    }
}

// ---------------- fused node2+node3: out = relu((h+agg)@w2+b2)@w3+b3 ----------------
// smem words: sT 16896 | sA 4608 | sB 4096 | sBias 256  = 25856 words
#define N23_SMEM_BYTES (25856 * 4)

__global__ void __launch_bounds__(256, 2)
node23_kernel(const float* __restrict__ h, const float* __restrict__ agg,
              const unsigned* __restrict__ w2p, const float* __restrict__ b2,
              const unsigned* __restrict__ w3p, const float* __restrict__ b3,
              float* __restrict__ out, int M) {
    extern __shared__ float smem[];
    unsigned* sT = (unsigned*)smem;        // 128 x 132
    unsigned* sA = sT + 16896;             // 128 x 36
    unsigned* sB = sA + 4608;              // 4096
    float* sBias = (float*)(sB + 4096);    // 256

    const int tid = threadIdx.x;
    const int lane = tid & 31;
    const int warp = tid >> 5;
    const int wm = warp >> 2, wn = warp & 3;
    const int m0 = blockIdx.x * 128;

    if (tid < 128) { sBias[tid] = b2[tid]; sBias[128 + tid] = b3[tid]; }
    __syncthreads();

    float acc[4][4][4];
    init_acc(acc, sBias, wn, lane);

    // GEMM1: (h+agg) @ w2, relu -> sT
#pragma unroll 1
    for (int kc = 0; kc < 4; kc++) {
#pragma unroll
        for (int i = 0; i < 4; i++) {
            int lin = tid + i * 256;
            int row = lin >> 3, c4 = lin & 7;
            float4 v = make_float4(0.f, 0.f, 0.f, 0.f);
            if (m0 + row < M) {
                v = *(const float4*)(h + (size_t)(m0 + row) * NCH + kc * 32 + c4 * 4);
                float4 w = *(const float4*)(agg + (size_t)(m0 + row) * NCH + kc * 32 + c4 * 4);
                v.x += w.x; v.y += w.y; v.z += w.z; v.w += w.w;
            }
            uint4 u;
            u.x = f2tf(v.x); u.y = f2tf(v.y); u.z = f2tf(v.z); u.w = f2tf(v.w);
            *(uint4*)&sA[row * 36 + c4 * 4] = u;
        }
        const uint4* bs = (const uint4*)(w2p + (size_t)kc * 4096);
#pragma unroll
        for (int i = 0; i < 4; i++)
            ((uint4*)sB)[tid + i * 256] = bs[tid + i * 256];
        __syncthreads();
        mma_chunk_rm(acc, sA, 36, 0, sB, wm, wn, lane);
        __syncthreads();
    }
    epi_tf32_relu(acc, sT, 132, wm, wn, lane);
    init_acc(acc, sBias + 128, wn, lane);
    __syncthreads();

    // GEMM2: t @ w3 -> out
#pragma unroll 1
    for (int kc = 0; kc < 4; kc++) {
        const uint4* bs = (const uint4*)(w3p + (size_t)kc * 4096);
#pragma unroll
        for (int i = 0; i < 4; i++)
            ((uint4*)sB)[tid + i * 256] = bs[tid + i * 256];
        __syncthreads();
        mma_chunk_rm(acc, sT, 132, kc * 32, sB, wm, wn, lane);
        __syncthreads();
    }

#pragma unroll
    for (int mt = 0; mt < 4; mt++) {
        int r0 = m0 + wm * 64 + mt * 16 + (lane >> 2);
#pragma unroll
        for (int nt = 0; nt < 4; nt++) {
            int c0 = wn * 32 + nt * 8 + (lane & 3) * 2;
            if (r0 < M)
                *(float2*)(out + (size_t)r0 * NCH + c0) =
                    make_float2(acc[mt][nt][0], acc[mt][nt][1]);
            if (r0 + 8 < M)
                *(float2*)(out + (size_t)(r0 + 8) * NCH + c0) =
                    make_float2(acc[mt][nt][2], acc[mt][nt][3]);
        }
    }
}

// ---------------- fused edge kernel (cp.async pipelined; R4-proven) ----------------
#define SMEM_WORDS (16896 + 8192 + 128 + 384 + 128 + 128)
#define SMEM_EDGE_BYTES (SMEM_WORDS * 4)
#define SM_STRIDE 132
#define SA_STRIDE 36
#define SA_BUF 4608

__device__ __forceinline__ const unsigned* chunk_src(const unsigned* wpack, int g) {
    if (g < 9)  return wpack + OFF_MW1 + (size_t)g * 4096;
    if (g < 13) return wpack + OFF_MW2 + (size_t)(g - 9) * 4096;
    return wpack + OFF_MW3 + (size_t)(g - 13) * 4096;
}

__global__ void __launch_bounds__(256, 2)
edge_kernel(const void* __restrict__ ei_raw, const float* __restrict__ eattr,
            const float* __restrict__ xpos, const unsigned* __restrict__ htf,
            float* __restrict__ agg, const unsigned* __restrict__ wpack,
            const float* __restrict__ mb1, const float* __restrict__ mb2,
            const float* __restrict__ mb3, int E) {
    extern __shared__ float smem[];
    unsigned* sM = (unsigned*)smem;              // 16896
    unsigned* sB0 = sM + 16896;                  // 4096
    unsigned* sB1 = sB0 + 4096;                  // 4096
    float* sR = (float*)(sB1 + 4096);            // 128
    float* sBiasAll = sR + 128;                  // 384
    int* sSrc = (int*)(sBiasAll + 384);          // 128
    int* sDst = sSrc + 128;                      // 128

    const unsigned smem_u32 = (unsigned)__cvta_generic_to_shared(smem);
    const unsigned sB_b[2] = { smem_u32 + 16896u * 4u, smem_u32 + (16896u + 4096u) * 4u };
    const unsigned sA_b[2] = { smem_u32, smem_u32 + (unsigned)SA_BUF * 4u };

    const int tid = threadIdx.x;
    const int lane = tid & 31;
    const int warp = tid >> 5;
    const int wm = warp >> 2, wn = warp & 3;
    const int e0 = blockIdx.x * 128;
    const int is64 = g_is64;

    // prologue
    if (tid < 128) {
        int e = e0 + tid;
        int s = 0, d = -1;
        float r = 0.f;
        if (e < E) {
            if (is64) {
                const long long* p = (const long long*)ei_raw;
                s = (int)p[e];
                d = (int)p[(size_t)E + e];
            } else {
                const int* p = (const int*)ei_raw;
                s = p[e];
                d = p[(size_t)E + e];
            }
            float dx = xpos[3 * d + 0] - xpos[3 * s + 0];
            float dy = xpos[3 * d + 1] - xpos[3 * s + 1];
            float dz = xpos[3 * d + 2] - xpos[3 * s + 2];
            r = sqrtf(dx * dx + dy * dy + dz * dz);
        }
        sSrc[tid] = s;
        sDst[tid] = d;
        sR[tid] = r;
        sBiasAll[tid] = mb1[tid];
        sBiasAll[128 + tid] = mb2[tid];
        sBiasAll[256 + tid] = mb3[tid];
    }
    __syncthreads();

    // features (stage-1 chunk 0 A) into sA buf0
    {
        const float INV2PI = 0.15915494309189535f;
        const float CA = 6.2831854820251465f;
        const float CB = -1.7484555e-7f;
        unsigned* sA0 = sM;
#pragma unroll
        for (int i = 0; i < 8; i++) {
            int lin = tid + i * 256;
            int row = lin >> 4, j = lin & 15;
            float omega = 10.f * exp2f(7.f - 0.875f * (float)j);
            float x = sR[row] * omega;
            float n = rintf(x * INV2PI);
            float rr = fmaf(-n, CA, x);
            rr = fmaf(-n, CB, rr);
            float sv, cv;
            sincosf(rr, &sv, &cv);
            sA0[row * SA_STRIDE + j] = f2tf(sv);
            sA0[row * SA_STRIDE + 16 + j] = f2tf(cv);
        }
    }

    // prefetch B chunk 0
#pragma unroll
    for (int i = 0; i < 4; i++) {
        int q = tid + i * 256;
        cpa16(sB_b[0] + q * 16, chunk_src(wpack, 0) + q * 4, 16);
    }
    cpa_commit();

    float acc[4][4][4];
    init_acc(acc, sBiasAll, wn, lane);

    // ---------------- stage 1: 9 chunks (K=288) ----------------
#pragma unroll 1
    for (int kc = 0; kc < 9; kc++) {
        __syncthreads();  // buf[(kc+1)&1] free
        if (kc < 8) {
            int g = kc + 1;
#pragma unroll
            for (int i = 0; i < 4; i++) {
                int lin = tid + i * 256;
                int row = lin >> 3, c4 = lin & 7;
                unsigned dst = sA_b[g & 1] + (unsigned)(row * SA_STRIDE + c4 * 4) * 4u;
                if (g < 5) {
                    int e = e0 + row;
                    const float* src = eattr + ((e < E) ? ((size_t)e * NCH + (g - 1) * 32 + c4 * 4) : 0);
                    cpa16(dst, src, (e < E) ? 16 : 0);
                } else {
                    const unsigned* src = htf + (size_t)sSrc[row] * NCH + (g - 5) * 32 + c4 * 4;
                    cpa16(dst, src, 16);
                }
            }
            const unsigned* bs = chunk_src(wpack, g);
#pragma unroll
            for (int i = 0; i < 4; i++) {
                int q = tid + i * 256;
                cpa16(sB_b[g & 1] + q * 16, bs + q * 4, 16);
            }
            cpa_commit();
            cpa_wait1();
        } else {
            cpa_wait0();
        }
        __syncthreads();  // chunk kc visible
        mma_chunk_rm(acc, sM + (kc & 1) * SA_BUF, SA_STRIDE, 0, (kc & 1) ? sB1 : sB0, wm, wn, lane);
    }

    // ---------------- boundary 1->2 ----------------
    __syncthreads();
    {
        const unsigned* bs = chunk_src(wpack, 9);
#pragma unroll
        for (int i = 0; i < 4; i++) {
            int q = tid + i * 256;
            cpa16(sB_b[0] + q * 16, bs + q * 4, 16);
        }
        cpa_commit();
    }
    epi_tf32_gelu(acc, sM, SM_STRIDE, wm, wn, lane);
    init_acc(acc, sBiasAll + 128, wn, lane);

    // ---------------- stage 2: 4 chunks ----------------
#pragma unroll 1
    for (int kc = 0; kc < 4; kc++) {
        __syncthreads();
        if (kc < 3) {
            const unsigned* bs = chunk_src(wpack, 10 + kc);
#pragma unroll
            for (int i = 0; i < 4; i++) {
                int q = tid + i * 256;
                cpa16(sB_b[(kc + 1) & 1] + q * 16, bs + q * 4, 16);
            }
            cpa_commit();
            cpa_wait1();
        } else {
            cpa_wait0();
        }
        __syncthreads();
        mma_chunk_rm(acc, sM, SM_STRIDE, kc * 32, (kc & 1) ? sB1 : sB0, wm, wn, lane);
    }

    // ---------------- boundary 2->3 ----------------
    __syncthreads();
    {
        const unsigned* bs = chunk_src(wpack, 13);
#pragma unroll
        for (int i = 0; i < 4; i++) {
            int q = tid + i * 256;
            cpa16(sB_b[0] + q * 16, bs + q * 4, 16);
        }
        cpa_commit();
    }
    epi_tf32_gelu(acc, sM, SM_STRIDE, wm, wn, lane);
    init_acc(acc, sBiasAll + 256, wn, lane);

    // ---------------- stage 3: 4 chunks ----------------
#pragma unroll 1
    for (int kc = 0; kc < 4; kc++) {
        __syncthreads();
        if (kc < 3) {
            const unsigned* bs = chunk_src(wpack, 14 + kc);
#pragma unroll
            for (int i = 0; i < 4; i++) {
                int q = tid + i * 256;
                cpa16(sB_b[(kc + 1) & 1] + q * 16, bs + q * 4, 16);
            }
            cpa_commit();
            cpa_wait1();
        } else {
            cpa_wait0();
        }
        __syncthreads();
        mma_chunk_rm(acc, sM, SM_STRIDE, kc * 32, (kc & 1) ? sB1 : sB0, wm, wn, lane);
    }
    __syncthreads();

    // stage-3 epilogue: fp32 row-major into sM
    float* sMf = (float*)sM;
#pragma unroll
    for (int mt = 0; mt < 4; mt++) {
        int r0 = wm * 64 + mt * 16 + (lane >> 2);
#pragma unroll
        for (int nt = 0; nt < 4; nt++) {
            int c0 = wn * 32 + nt * 8 + (lane & 3) * 2;
            *(float2*)&sMf[r0 * SM_STRIDE + c0] = make_float2(acc[mt][nt][0], acc[mt][nt][1]);
            *(float2*)&sMf[(r0 + 8) * SM_STRIDE + c0] = make_float2(acc[mt][nt][2], acc[mt][nt][3]);
        }
    }
    __syncthreads();

    // scatter: agg[dst] += m
#pragma unroll
    for (int i = 0; i < 16; i++) {
        int lin = tid + i * 256;
        int row = lin >> 5, c4 = lin & 31;
        int d = sDst[row];
        if (d >= 0) {
            float4 v = *(float4*)&sMf[row * SM_STRIDE + c4 * 4];
            float* p = agg + (size_t)d * NCH + c4 * 4;
            asm volatile("red.global.add.v4.f32 [%0], {%1,%2,%3,%4};" ::
                             "l"(p), "f"(v.x), "f"(v.y), "f"(v.z), "f"(v.w)
                         : "memory");
        }
    }
}

// ---------------- launch ----------------
extern "C" void kernel_launch(void* const* d_in, const int* in_sizes, int n_in,
                              void* d_out, int out_size) {
    const float* x     = (const float*)d_in[0];
    const void*  ei    = d_in[1];
    const float* eattr = (const float*)d_in[2];
    const float* xpos  = (const float*)d_in[3];
    const float* w1  = (const float*)d_in[4];
    const float* b1  = (const float*)d_in[5];
    const float* mw1 = (const float*)d_in[6];
    const float* mb1 = (const float*)d_in[7];
    const float* mw2 = (const float*)d_in[8];
    const float* mb2 = (const float*)d_in[9];
    const float* mw3 = (const float*)d_in[10];
    const float* mb3 = (const float*)d_in[11];
    const float* w2  = (const float*)d_in[12];
    const float* b2  = (const float*)d_in[13];
    const float* w3  = (const float*)d_in[14];
    const float* b3  = (const float*)d_in[15];

    int N = in_sizes[0] / NCH;
    int E = in_sizes[1] / 2;
    float* out = (float*)d_out;

    float *hptr, *aptr;
    unsigned *wp, *htf;
    cudaGetSymbolAddress((void**)&hptr, g_h);
    cudaGetSymbolAddress((void**)&aptr, g_agg);
    cudaGetSymbolAddress((void**)&wp, g_wpack);
    cudaGetSymbolAddress((void**)&htf, g_htf);

    cudaFuncSetAttribute(edge_kernel, cudaFuncAttributeMaxDynamicSharedMemorySize,
                         SMEM_EDGE_BYTES);
    cudaFuncSetAttribute(node23_kernel, cudaFuncAttributeMaxDynamicSharedMemorySize,
                         N23_SMEM_BYTES);

    // launch 1 (3rd overall)
    prep_all<<<(118784 + 255) / 256, 256>>>(mw1, mw2, mw3, w1, w2, w3, ei, wp);
    // launch 2
    int n4 = N * NCH / 4;
    zero_kernel<<<(n4 + 255) / 256, 256>>>((float4*)aptr, n4);
    // launch 3
    node_gemm<<<(N + 127) / 128, 256>>>(x, wp + OFF_W1, b1, hptr, htf, N);
    // launch 4 (6th overall -> ncu -s 5 -c 1 captures this)
    edge_kernel<<<(E + 127) / 128, 256, SMEM_EDGE_BYTES>>>(
        ei, eattr, xpos, htf, aptr, wp, mb1, mb2, mb3, E);
    // launch 5
    node23_kernel<<<(N + 127) / 128, 256, N23_SMEM_BYTES>>>(
        hptr, aptr, wp + OFF_W2, b2, wp + OFF_W3, b3, out, N);
}